// round 1
// baseline (speedup 1.0000x reference)
#include <cuda_runtime.h>
#include <math.h>

// Problem constants
#define B_TOT   4096
#define NOBJ    64
#define DOBJ    32
#define FEAT    31
#define HID     256
#define OBS_W   2304
#define OTH_OFF 2048
#define NHEAD   4
#define HDIM    64
#define PITCH   260   // float pitch for 64x256 tiles: mult of 4 (float4 align), mod 32 = 4

struct SmemLayout {
    float feats[NOBJ * DOBJ];     // 2048 floats  (objs raw; [n*32 + d], d=31 is mask)
    float A[NOBJ * PITCH];        // 16640 floats (H1, then rawP)
    float Bf[NOBJ * PITCH];       // 16640 floats (H2)
    float v0[HID];                // stage-A ping
    float v1[HID];                // stage-A pong
    float qt[HID];                // q~ = Wk[h] @ q[h]
    float qb[NHEAD];              // q . bk per head
    float mask[NOBJ];
    float logit[NHEAD * NOBJ];
    float wgt[NHEAD * NOBJ];      // attn * mask^2
    float Th[NHEAD];              // sum attn * mask
    float Svec[NHEAD * HDIM];     // weighted rawP sum per head
};

// out[r][j] = act(bias[j] + sum_k sIn[r*PIN+k] * W[k*HID+j]) for r=0..63, thread j owns one column.
template<int KIN, int PIN, bool RELU>
__device__ __forceinline__ void obj_gemm(const float* __restrict__ W,
                                         const float* __restrict__ bias,
                                         const float* sIn, float* sOut, int j)
{
    float acc[NOBJ];
    const float bb = bias[j];
#pragma unroll
    for (int r = 0; r < NOBJ; r++) acc[r] = bb;

    constexpr int KT = (KIN / 4) * 4;
    for (int k0 = 0; k0 < KT; k0 += 4) {
        const float w0 = W[(k0 + 0) * HID + j];
        const float w1 = W[(k0 + 1) * HID + j];
        const float w2 = W[(k0 + 2) * HID + j];
        const float w3 = W[(k0 + 3) * HID + j];
#pragma unroll
        for (int r = 0; r < NOBJ; r++) {
            const float4 v = *reinterpret_cast<const float4*>(&sIn[r * PIN + k0]);
            acc[r] = fmaf(v.x, w0, acc[r]);
            acc[r] = fmaf(v.y, w1, acc[r]);
            acc[r] = fmaf(v.z, w2, acc[r]);
            acc[r] = fmaf(v.w, w3, acc[r]);
        }
    }
    for (int k = KT; k < KIN; k++) {
        const float w = W[k * HID + j];
#pragma unroll
        for (int r = 0; r < NOBJ; r++)
            acc[r] = fmaf(sIn[r * PIN + k], w, acc[r]);
    }
#pragma unroll
    for (int r = 0; r < NOBJ; r++) {
        float x = acc[r];
        if (RELU) x = fmaxf(x, 0.0f);
        sOut[r * PITCH + j] = x;
    }
}

__global__ void __launch_bounds__(256, 1) pinet_kernel(
    const float* __restrict__ obs,
    const float* __restrict__ oW1, const float* __restrict__ ob1,
    const float* __restrict__ oW2, const float* __restrict__ ob2,
    const float* __restrict__ pW1, const float* __restrict__ pb1,
    const float* __restrict__ pW2, const float* __restrict__ pb2,
    const float* __restrict__ pW3, const float* __restrict__ pb3,
    const float* __restrict__ Wq,  const float* __restrict__ bq,
    const float* __restrict__ Wk,  const float* __restrict__ bk,
    const float* __restrict__ Wv,  const float* __restrict__ bv,
    float* __restrict__ out)
{
    extern __shared__ float smraw[];
    SmemLayout* s = reinterpret_cast<SmemLayout*>(smraw);

    const int b   = blockIdx.x;
    const int tid = threadIdx.x;
    const float* row = obs + (size_t)b * OBS_W;

    // ---- load objects (2048 floats) + others (256 floats) ----
    {
        const float4* r4 = reinterpret_cast<const float4*>(row);
        float4* f4 = reinterpret_cast<float4*>(s->feats);
        f4[tid]       = r4[tid];
        f4[tid + 256] = r4[tid + 256];
        s->v0[tid] = row[OTH_OFF + tid];
    }
    __syncthreads();
    if (tid < NOBJ) s->mask[tid] = s->feats[tid * DOBJ + (DOBJ - 1)];

    // ================= Stage A: per-sample path =================
    // others layer 1 (ReLU)
    {
        float a = ob1[tid];
        for (int k = 0; k < HID; k += 4) {
            const float4 v = *reinterpret_cast<const float4*>(&s->v0[k]);
            a = fmaf(v.x, oW1[(k + 0) * HID + tid], a);
            a = fmaf(v.y, oW1[(k + 1) * HID + tid], a);
            a = fmaf(v.z, oW1[(k + 2) * HID + tid], a);
            a = fmaf(v.w, oW1[(k + 3) * HID + tid], a);
        }
        s->v1[tid] = fmaxf(a, 0.0f);
    }
    __syncthreads();
    // others layer 2 (no ReLU) -> others_e ; write first half of output
    {
        float a = ob2[tid];
        for (int k = 0; k < HID; k += 4) {
            const float4 v = *reinterpret_cast<const float4*>(&s->v1[k]);
            a = fmaf(v.x, oW2[(k + 0) * HID + tid], a);
            a = fmaf(v.y, oW2[(k + 1) * HID + tid], a);
            a = fmaf(v.z, oW2[(k + 2) * HID + tid], a);
            a = fmaf(v.w, oW2[(k + 3) * HID + tid], a);
        }
        out[(size_t)b * 512 + tid] = a;
        s->v0[tid] = a;
    }
    __syncthreads();
    // q = others_e @ Wq + bq
    {
        float a = bq[tid];
        for (int k = 0; k < HID; k += 4) {
            const float4 v = *reinterpret_cast<const float4*>(&s->v0[k]);
            a = fmaf(v.x, Wq[(k + 0) * HID + tid], a);
            a = fmaf(v.y, Wq[(k + 1) * HID + tid], a);
            a = fmaf(v.z, Wq[(k + 2) * HID + tid], a);
            a = fmaf(v.w, Wq[(k + 3) * HID + tid], a);
        }
        s->v1[tid] = a;   // q, head-major
    }
    __syncthreads();
    // qt[h*64+d] = sum_e Wk[h,d,e]*q[h,e] ; qb[h] = q[h,:].bk[h,:]
    {
        const int h = tid >> 6, d = tid & 63;
        const float4* wk4 = reinterpret_cast<const float4*>(Wk + h * (HDIM * HDIM) + d * HDIM);
        const float4* q4  = reinterpret_cast<const float4*>(s->v1 + h * HDIM);
        float t = 0.0f;
#pragma unroll
        for (int e = 0; e < HDIM / 4; e++) {
            const float4 w = wk4[e];
            const float4 qv = q4[e];
            t += w.x * qv.x + w.y * qv.y + w.z * qv.z + w.w * qv.w;
        }
        s->qt[tid] = t;
        if (tid < NHEAD) {
            float sb = 0.0f;
            for (int e = 0; e < HDIM; e++) sb += s->v1[tid * HDIM + e] * bk[tid * HDIM + e];
            s->qb[tid] = sb;
        }
    }
    __syncthreads();

    // ================= Stage B: per-object MLP (the 73 GFLOP part) =================
    obj_gemm<FEAT, DOBJ,  true >(pW1, pb1, s->feats, s->A,  tid);  // H1  -> A
    __syncthreads();
    obj_gemm<HID,  PITCH, true >(pW2, pb2, s->A,     s->Bf, tid);  // H2  -> Bf
    __syncthreads();
    obj_gemm<HID,  PITCH, false>(pW3, pb3, s->Bf,    s->A,  tid);  // rawP -> A  (pre-mask emb)
    __syncthreads();

    // ================= Stage C: attention (q-len 1, K/V folded away) =================
    const int h = tid >> 6;
    const int n = tid & 63;
    {
        const float* rp = s->A + n * PITCH + h * HDIM;
        const float* qt = s->qt + h * HDIM;
        float dot = 0.0f;
#pragma unroll
        for (int d = 0; d < HDIM; d += 4) {
            const float4 a4 = *reinterpret_cast<const float4*>(&rp[d]);
            const float4 b4 = *reinterpret_cast<const float4*>(&qt[d]);
            dot += a4.x * b4.x + a4.y * b4.y + a4.z * b4.z + a4.w * b4.w;
        }
        const float m = s->mask[n];
        float lg = fmaf(m, dot, s->qb[h]) * 0.0625f;   // / sqrt(256)
        if (m == 0.0f) lg = -1000000000.0f;
        s->logit[h * NOBJ + n] = lg;
    }
    __syncthreads();

    // softmax per head (warps 0..3, head = warp id), plus wgt = attn*mask^2, Th = sum attn*mask
    {
        const int wid = tid >> 5, lane = tid & 31;
        if (wid < NHEAD) {
            const int hh = wid;
            const float x0 = s->logit[hh * NOBJ + lane];
            const float x1 = s->logit[hh * NOBJ + 32 + lane];
            float mx = fmaxf(x0, x1);
#pragma unroll
            for (int o = 16; o > 0; o >>= 1) mx = fmaxf(mx, __shfl_xor_sync(0xffffffffu, mx, o));
            const float e0 = expf(x0 - mx);
            const float e1 = expf(x1 - mx);
            float sum = e0 + e1;
#pragma unroll
            for (int o = 16; o > 0; o >>= 1) sum += __shfl_xor_sync(0xffffffffu, sum, o);
            const float inv = 1.0f / sum;
            const float a0 = e0 * inv, a1 = e1 * inv;
            const float m0 = s->mask[lane], m1 = s->mask[32 + lane];
            s->wgt[hh * NOBJ + lane]      = a0 * m0 * m0;
            s->wgt[hh * NOBJ + 32 + lane] = a1 * m1 * m1;
            float tt = a0 * m0 + a1 * m1;
#pragma unroll
            for (int o = 16; o > 0; o >>= 1) tt += __shfl_xor_sync(0xffffffffu, tt, o);
            if (lane == 0) s->Th[hh] = tt;
        }
    }
    __syncthreads();

    // Svec[h,d] = sum_n wgt[h,n] * rawP[n, h*64+d]
    {
        const int d = tid & 63;
        const float* wp = s->wgt + h * NOBJ;
        float acc = 0.0f;
#pragma unroll 4
        for (int nn = 0; nn < NOBJ; nn++)
            acc = fmaf(wp[nn], s->A[nn * PITCH + h * HDIM + d], acc);
        s->Svec[tid] = acc;
    }
    __syncthreads();

    // out_emb[h,e] = Svec[h,:] @ Wv[h] + Th[h]*bv[h,e]
    {
        const int e = tid & 63;
        float o = s->Th[h] * bv[h * HDIM + e];
        const float* sv = s->Svec + h * HDIM;
        const float* wv = Wv + h * (HDIM * HDIM) + e;
#pragma unroll 4
        for (int d = 0; d < HDIM; d++)
            o = fmaf(sv[d], wv[d * HDIM], o);
        out[(size_t)b * 512 + 256 + h * HDIM + e] = o;
    }
}

extern "C" void kernel_launch(void* const* d_in, const int* in_sizes, int n_in,
                              void* d_out, int out_size)
{
    const float* obs = (const float*)d_in[0];
    const float* oW1 = (const float*)d_in[1];
    const float* ob1 = (const float*)d_in[2];
    const float* oW2 = (const float*)d_in[3];
    const float* ob2 = (const float*)d_in[4];
    const float* pW1 = (const float*)d_in[5];
    const float* pb1 = (const float*)d_in[6];
    const float* pW2 = (const float*)d_in[7];
    const float* pb2 = (const float*)d_in[8];
    const float* pW3 = (const float*)d_in[9];
    const float* pb3 = (const float*)d_in[10];
    const float* Wq  = (const float*)d_in[11];
    const float* bq  = (const float*)d_in[12];
    const float* Wk  = (const float*)d_in[13];
    const float* bk  = (const float*)d_in[14];
    const float* Wv  = (const float*)d_in[15];
    const float* bv  = (const float*)d_in[16];
    float* out = (float*)d_out;

    const int smem = (int)sizeof(SmemLayout);
    cudaFuncSetAttribute(pinet_kernel, cudaFuncAttributeMaxDynamicSharedMemorySize, smem);
    pinet_kernel<<<B_TOT, 256, smem>>>(obs, oW1, ob1, oW2, ob2,
                                       pW1, pb1, pW2, pb2, pW3, pb3,
                                       Wq, bq, Wk, bk, Wv, bv, out);
}